// round 1
// baseline (speedup 1.0000x reference)
#include <cuda_runtime.h>
#include <cuda_bf16.h>

// ---------------- problem constants ----------------
#define B_    2
#define L_    1024
#define DM_   1024
#define DI_   2048
#define NSO_  16      // outer state dim
#define KC_   4       // outer conv width
#define DTR_  64
#define MDI_  64
#define MNS_  4       // inner state dim
#define MKC_  2       // inner conv width

// ---------------- scratch (device globals; no allocation allowed) ----------
__device__ float g_xz   [(size_t)B_ * 2 * DI_ * L_];   // in_proj out [b, 2DI, L]
__device__ float g_xc   [(size_t)B_ * DI_ * L_];       // conv+silu x [b, DI, L]
__device__ float g_xdbl [(size_t)B_ * L_ * 96];        // x_proj out  [b, L, 96]
__device__ float g_mxz  [(size_t)B_ * 2 * MDI_ * L_];  // inner in_proj [b,128,L]
__device__ float g_mxc  [(size_t)B_ * MDI_ * L_];      // inner conv+silu
__device__ float g_mxdbl[(size_t)B_ * L_ * 12];        // inner x_proj [b,L,12]
__device__ float g_mdel [(size_t)B_ * MDI_ * L_];      // inner delta
__device__ float g_myi  [(size_t)B_ * MDI_ * L_];      // inner scan out
__device__ float g_dtm  [(size_t)B_ * L_ * DTR_];      // dt_m [b,L,64]
__device__ float g_del  [(size_t)B_ * DI_ * L_];       // outer delta
__device__ float g_y    [(size_t)B_ * DI_ * L_];       // outer scan out

// ---------------- generic strided fp32 GEMM ----------------
// C[b,i,j] = sum_k A[b*aB + i*aI + k*aK] * B[b*bB + j*bJ + k*bK]
// 64x64 tile per block, 256 threads, 4x4 micro-tile, BK=16.
__global__ void gemm64(const float* __restrict__ A, const float* __restrict__ B,
                       float* __restrict__ C, int M, int N, int K,
                       long long aB, long long aI, long long aK,
                       long long bB, long long bJ, long long bK,
                       long long cB, long long cI, long long cJ)
{
    __shared__ float As[16][65];
    __shared__ float Bs[16][65];
    int bz = blockIdx.z;
    int i0 = blockIdx.y * 64;
    int j0 = blockIdx.x * 64;
    int tid = threadIdx.x;            // 0..255
    int tx = tid & 15, ty = tid >> 4; // 16x16
    const float* Ab = A + (long long)bz * aB;
    const float* Bb = B + (long long)bz * bB;

    float acc[4][4];
#pragma unroll
    for (int r = 0; r < 4; r++)
#pragma unroll
        for (int c = 0; c < 4; c++) acc[r][c] = 0.f;

    bool aKfast = (aK == 1);
    bool bKfast = (bK == 1);

    for (int kt = 0; kt < K; kt += 16) {
#pragma unroll
        for (int t = 0; t < 4; t++) {
            int idx = tid + t * 256;  // 0..1023 covers 64i x 16k
            // A tile
            {
                int k, i;
                if (aKfast) { k = idx & 15; i = idx >> 4; }
                else        { i = idx & 63; k = idx >> 6; }
                int gi = i0 + i, gk = kt + k;
                float v = 0.f;
                if (gi < M && gk < K)
                    v = Ab[(long long)gi * aI + (long long)gk * aK];
                As[k][i] = v;
            }
            // B tile
            {
                int k, j;
                if (bKfast) { k = idx & 15; j = idx >> 4; }
                else        { j = idx & 63; k = idx >> 6; }
                int gj = j0 + j, gk = kt + k;
                float v = 0.f;
                if (gj < N && gk < K)
                    v = Bb[(long long)gj * bJ + (long long)gk * bK];
                Bs[k][j] = v;
            }
        }
        __syncthreads();
#pragma unroll
        for (int kk = 0; kk < 16; kk++) {
            float a[4], b[4];
#pragma unroll
            for (int r = 0; r < 4; r++) a[r] = As[kk][ty * 4 + r];
#pragma unroll
            for (int c = 0; c < 4; c++) b[c] = Bs[kk][tx * 4 + c];
#pragma unroll
            for (int r = 0; r < 4; r++)
#pragma unroll
                for (int c = 0; c < 4; c++) acc[r][c] += a[r] * b[c];
        }
        __syncthreads();
    }

    float* Cb = C + (long long)bz * cB;
#pragma unroll
    for (int r = 0; r < 4; r++) {
        int gi = i0 + ty * 4 + r;
        if (gi >= M) continue;
#pragma unroll
        for (int c = 0; c < 4; c++) {
            int gj = j0 + tx * 4 + c;
            if (gj < N)
                Cb[(long long)gi * cI + (long long)gj * cJ] = acc[r][c];
        }
    }
}

// ---------------- depthwise causal conv1d + bias + SiLU ----------------
// in index: b*in_bs + d*Lx + l    out: [Bn, D, Lx] contiguous
__global__ void conv_silu_kernel(const float* __restrict__ in, long long in_bs,
                                 const float* __restrict__ w,
                                 const float* __restrict__ bias,
                                 float* __restrict__ out,
                                 int Bn, int D, int Lx, int Kc)
{
    long long idx = (long long)blockIdx.x * blockDim.x + threadIdx.x;
    long long total = (long long)Bn * D * Lx;
    if (idx >= total) return;
    int l = (int)(idx % Lx);
    int d = (int)((idx / Lx) % D);
    int b = (int)(idx / ((long long)Lx * D));
    const float* xin = in + (long long)b * in_bs + (long long)d * Lx;
    float acc = bias[d];
    for (int k = 0; k < Kc; k++) {
        int li = l - (Kc - 1) + k;
        if (li >= 0) acc += w[d * Kc + k] * xin[li];
    }
    out[idx] = acc * (1.f / (1.f + __expf(-acc)));   // silu
}

// ---------------- selective scan ----------------
// lane-per-state layout: NS lanes form one channel, 32/NS channels per warp.
// y[b,d,l] = (sum_n s_n * C[b,n,l] + u*D[d]) * silu(z[b,d,l])
// s_n <- exp(dt*A[d,n]) * s_n + dt*B[b,n,l]*u,  dt = softplus(delta + bias[d])
template <int NS>
__global__ void scan_kernel(const float* __restrict__ delta, long long d_bs,
                            const float* __restrict__ dt_bias,
                            const float* __restrict__ A_log,
                            const float* __restrict__ u, long long u_bs,
                            const float* __restrict__ bc, int bcRow, int bOff, int cOff,
                            const float* __restrict__ Dp,
                            const float* __restrict__ z, long long z_bs,
                            float* __restrict__ y, long long y_bs,
                            int Bn, int Dch, int Lx)
{
    const int WPC = 32 / NS;
    int lane = threadIdx.x & 31;
    int warp = (blockIdx.x * blockDim.x + threadIdx.x) >> 5;
    int n = lane % NS;
    int ch = warp * WPC + lane / NS;
    if (ch >= Bn * Dch) return;
    int b = ch / Dch, d = ch % Dch;

    float An   = -__expf(A_log[d * NS + n]);
    float Dd   = Dp[d];
    float bias = dt_bias[d];
    const float* dl  = delta + (long long)b * d_bs + (long long)d * Lx;
    const float* ul  = u     + (long long)b * u_bs + (long long)d * Lx;
    const float* zl  = z     + (long long)b * z_bs + (long long)d * Lx;
    const float* bcb = bc + (long long)b * Lx * bcRow;
    float* yl = y + (long long)b * y_bs + (long long)d * Lx;

    float s = 0.f;
    for (int l = 0; l < Lx; l++) {
        float t  = dl[l] + bias;
        float dt = (t > 20.f) ? t : log1pf(__expf(t));
        float uu = ul[l];
        const float* row = bcb + (long long)l * bcRow;
        float Bv = row[bOff + n];
        float Cv = row[cOff + n];
        s = __expf(dt * An) * s + dt * Bv * uu;
        float yp = s * Cv;
#pragma unroll
        for (int off = NS / 2; off > 0; off >>= 1)
            yp += __shfl_xor_sync(0xffffffffu, yp, off);
        if (n == 0) {
            float zz = zl[l];
            yl[l] = (yp + uu * Dd) * zz * (1.f / (1.f + __expf(-zz)));
        }
    }
}

// ---------------- launch ----------------
extern "C" void kernel_launch(void* const* d_in, const int* in_sizes, int n_in,
                              void* d_out, int out_size)
{
    const float* h         = (const float*)d_in[0];   // [2,1024,1024]
    const float* in_proj_w = (const float*)d_in[1];   // [4096,1024]
    const float* conv_w    = (const float*)d_in[2];   // [2048,4]
    const float* conv_b    = (const float*)d_in[3];   // [2048]
    const float* x_proj_w  = (const float*)d_in[4];   // [96,2048]
    const float* A_log     = (const float*)d_in[5];   // [2048,16]
    const float* Dvec      = (const float*)d_in[6];   // [2048]
    const float* dt_out_w  = (const float*)d_in[7];   // [2048,64]
    const float* dt_out_b  = (const float*)d_in[8];   // [2048]
    const float* out_w     = (const float*)d_in[9];   // [1024,2048]
    const float* m_in_w    = (const float*)d_in[10];  // [128,64]
    const float* m_conv_w  = (const float*)d_in[11];  // [64,2]
    const float* m_conv_b  = (const float*)d_in[12];  // [64]
    const float* m_x_proj_w= (const float*)d_in[13];  // [12,64]
    const float* m_dt_w    = (const float*)d_in[14];  // [64,4]
    const float* m_dt_b    = (const float*)d_in[15];  // [64]
    const float* m_A_log   = (const float*)d_in[16];  // [64,4]
    const float* m_D       = (const float*)d_in[17];  // [64]
    const float* m_out_w   = (const float*)d_in[18];  // [64,64]
    float* out = (float*)d_out;                       // [2,1024,1024]

    float *xz, *xc, *xdbl, *mxz, *mxc, *mxdbl, *mdel, *myi, *dtm, *del, *y;
    cudaGetSymbolAddress((void**)&xz,    g_xz);
    cudaGetSymbolAddress((void**)&xc,    g_xc);
    cudaGetSymbolAddress((void**)&xdbl,  g_xdbl);
    cudaGetSymbolAddress((void**)&mxz,   g_mxz);
    cudaGetSymbolAddress((void**)&mxc,   g_mxc);
    cudaGetSymbolAddress((void**)&mxdbl, g_mxdbl);
    cudaGetSymbolAddress((void**)&mdel,  g_mdel);
    cudaGetSymbolAddress((void**)&myi,   g_myi);
    cudaGetSymbolAddress((void**)&dtm,   g_dtm);
    cudaGetSymbolAddress((void**)&del,   g_del);
    cudaGetSymbolAddress((void**)&y,     g_y);

    const long long LL = L_;

    // 1) xz[b,e,l] = sum_d in_proj_w[e,d] * h[b,l,d]   (M=4096,N=1024,K=1024)
    gemm64<<<dim3(L_ / 64, (2 * DI_) / 64, B_), 256>>>(
        in_proj_w, h, xz, 2 * DI_, L_, DM_,
        0LL, (long long)DM_, 1LL,
        (long long)L_ * DM_, (long long)DM_, 1LL,
        (long long)2 * DI_ * L_, LL, 1LL);

    // 2) x = silu(conv(x) + b)
    {
        long long total = (long long)B_ * DI_ * L_;
        conv_silu_kernel<<<(int)((total + 255) / 256), 256>>>(
            xz, (long long)2 * DI_ * L_, conv_w, conv_b, xc, B_, DI_, L_, KC_);
    }

    // 3) x_dbl[b,l,e] = sum_d xc[b,d,l] * x_proj_w[e,d]  (M=1024,N=96,K=2048)
    gemm64<<<dim3(2, L_ / 64, B_), 256>>>(
        xc, x_proj_w, xdbl, L_, 96, DI_,
        (long long)DI_ * L_, 1LL, LL,
        0LL, (long long)DI_, 1LL,
        (long long)L_ * 96, 96LL, 1LL);

    // 4a) inner in_proj: mxz[b,e,l] = sum_r m_in_w[e,r] * dt_in[b,l,r]
    gemm64<<<dim3(L_ / 64, 2, B_), 256>>>(
        m_in_w, xdbl, mxz, 2 * MDI_, L_, DTR_,
        0LL, (long long)DTR_, 1LL,
        (long long)L_ * 96, 96LL, 1LL,
        (long long)2 * MDI_ * L_, LL, 1LL);

    // 4b) inner conv+silu
    {
        long long total = (long long)B_ * MDI_ * L_;
        conv_silu_kernel<<<(int)((total + 255) / 256), 256>>>(
            mxz, (long long)2 * MDI_ * L_, m_conv_w, m_conv_b, mxc, B_, MDI_, L_, MKC_);
    }

    // 4c) inner x_proj: mxdbl[b,l,e] = sum_d mxc[b,d,l] * m_x_proj_w[e,d]
    gemm64<<<dim3(1, L_ / 64, B_), 256>>>(
        mxc, m_x_proj_w, mxdbl, L_, 12, MDI_,
        (long long)MDI_ * L_, 1LL, LL,
        0LL, (long long)MDI_, 1LL,
        (long long)L_ * 12, 12LL, 1LL);

    // 4d) inner delta: mdel[b,d,l] = sum_r m_dt_w[d,r] * mxdbl[b,l,r]
    gemm64<<<dim3(L_ / 64, 1, B_), 256>>>(
        m_dt_w, mxdbl, mdel, MDI_, L_, 4,
        0LL, 4LL, 1LL,
        (long long)L_ * 12, 12LL, 1LL,
        (long long)MDI_ * L_, LL, 1LL);

    // 4e) inner scan (NS=4): channels = 2*64 = 128 -> 2 blocks of 256
    scan_kernel<MNS_><<<2, 256>>>(
        mdel, (long long)MDI_ * L_,
        m_dt_b, m_A_log,
        mxc, (long long)MDI_ * L_,
        mxdbl, 12, 4, 8,
        m_D,
        mxz + (long long)MDI_ * L_, (long long)2 * MDI_ * L_,
        myi, (long long)MDI_ * L_,
        B_, MDI_, L_);

    // 4f) dt_m[b,l,o] = sum_d myi[b,d,l] * m_out_w[o,d]
    gemm64<<<dim3(1, L_ / 64, B_), 256>>>(
        myi, m_out_w, dtm, L_, DTR_, MDI_,
        (long long)MDI_ * L_, 1LL, LL,
        0LL, (long long)MDI_, 1LL,
        (long long)L_ * DTR_, (long long)DTR_, 1LL);

    // 5) delta[b,d,l] = sum_r dt_out_w[d,r] * dtm[b,l,r]  (M=2048,N=1024,K=64)
    gemm64<<<dim3(L_ / 64, DI_ / 64, B_), 256>>>(
        dt_out_w, dtm, del, DI_, L_, DTR_,
        0LL, (long long)DTR_, 1LL,
        (long long)L_ * DTR_, (long long)DTR_, 1LL,
        (long long)DI_ * L_, LL, 1LL);

    // 6) outer scan (NS=16): channels = 2*2048 = 4096 -> 256 blocks of 256
    scan_kernel<NSO_><<<256, 256>>>(
        del, (long long)DI_ * L_,
        dt_out_b, A_log,
        xc, (long long)DI_ * L_,
        xdbl, 96, 64, 80,
        Dvec,
        xz + (long long)DI_ * L_, (long long)2 * DI_ * L_,
        y, (long long)DI_ * L_,
        B_, DI_, L_);

    // 7) out[b,l,o] = sum_d y[b,d,l] * out_w[o,d]  (M=1024,N=1024,K=2048)
    gemm64<<<dim3(DM_ / 64, L_ / 64, B_), 256>>>(
        y, out_w, out, L_, DM_, DI_,
        (long long)DI_ * L_, 1LL, LL,
        0LL, (long long)DI_, 1LL,
        (long long)L_ * DM_, (long long)DM_, 1LL);
}

// round 2
// speedup vs baseline: 1.1895x; 1.1895x over previous
#include <cuda_runtime.h>
#include <cuda_bf16.h>
#include <cstdint>

// ---------------- problem constants ----------------
#define B_    2
#define L_    1024
#define DM_   1024
#define DI_   2048
#define NSO_  16      // outer state dim
#define KC_   4       // outer conv width
#define DTR_  64
#define MDI_  64
#define MNS_  4       // inner state dim
#define MKC_  2       // inner conv width

// ---------------- scratch (device globals; no allocation allowed) ----------
__device__ float g_xz   [(size_t)B_ * 2 * DI_ * L_];   // in_proj out [b, 2DI, L]
__device__ float g_xc   [(size_t)B_ * DI_ * L_];       // conv+silu x [b, DI, L]
__device__ float g_xdbl [(size_t)B_ * L_ * 96];        // x_proj out  [b, L, 96]
__device__ float g_mxz  [(size_t)B_ * 2 * MDI_ * L_];  // inner in_proj [b,128,L]
__device__ float g_mxc  [(size_t)B_ * MDI_ * L_];      // inner conv+silu
__device__ float g_mxdbl[(size_t)B_ * L_ * 12];        // inner x_proj [b,L,12]
__device__ float g_mdel [(size_t)B_ * MDI_ * L_];      // inner delta
__device__ float g_myi  [(size_t)B_ * MDI_ * L_];      // inner scan out
__device__ float g_dtm  [(size_t)B_ * L_ * DTR_];      // dt_m [b,L,64]
__device__ float g_del  [(size_t)B_ * DI_ * L_];       // outer delta
__device__ float g_y    [(size_t)B_ * DI_ * L_];       // outer scan out

// ---------------- tf32 tensor-core GEMM ----------------
// C[b,i,j] = sum_k A[b*aB + i*aI + k*aK] * B[b*bB + j*bJ + k*bK]
// 128x128 tile, BK=32, 256 threads (8 warps, 2x4), mma.sync m16n8k8 tf32.
// smem layout [row][k] with row stride 36 floats -> conflict-free frag loads.
__device__ __forceinline__ uint32_t f2tf32(float x) {
    uint32_t u;
    asm("cvt.rna.tf32.f32 %0, %1;" : "=r"(u) : "f"(x));
    return u;
}

__global__ void __launch_bounds__(256, 2) gemm_tc(
    const float* __restrict__ A, const float* __restrict__ B,
    float* __restrict__ C, int M, int N, int K,
    long long aB, long long aI, long long aK,
    long long bB, long long bJ, long long bK,
    long long cB, long long cI, long long cJ)
{
    __shared__ float As[128][36];
    __shared__ float Bs[128][36];

    int bz = blockIdx.z;
    int i0 = blockIdx.y * 128;
    int j0 = blockIdx.x * 128;
    int tid = threadIdx.x;
    int lane = tid & 31, warp = tid >> 5;
    int wm = warp & 1;          // 0..1  -> 64 rows each
    int wn = warp >> 1;         // 0..3  -> 32 cols each
    int gid = lane >> 2, t4 = lane & 3;

    const float* Ab = A + (long long)bz * aB;
    const float* Bb = B + (long long)bz * bB;

    float acc[4][4][4] = {};

    const bool aKf = (aK == 1);
    const bool bKf = (bK == 1);

    for (int kt = 0; kt < K; kt += 32) {
        // ---- stage A tile (128 rows x 32 k) ----
        if (aKf) {
#pragma unroll
            for (int it = 0; it < 4; it++) {
                int idx = tid + it * 256;        // 1024 float4 slots
                int i = idx >> 3, kq = (idx & 7) * 4;
                int gi = i0 + i;
                float4 v = make_float4(0.f, 0.f, 0.f, 0.f);
                if (gi < M)
                    v = *(const float4*)(Ab + (long long)gi * aI + (kt + kq));
                *(float4*)(&As[i][kq]) = v;
            }
        } else {
#pragma unroll
            for (int it = 0; it < 16; it++) {
                int idx = tid + it * 256;        // 4096 scalar slots
                int i = idx & 127, k = idx >> 7;
                int gi = i0 + i;
                float v = 0.f;
                if (gi < M)
                    v = Ab[(long long)gi * aI + (long long)(kt + k) * aK];
                As[i][k] = v;
            }
        }
        // ---- stage B tile (128 cols x 32 k) ----
        if (bKf) {
#pragma unroll
            for (int it = 0; it < 4; it++) {
                int idx = tid + it * 256;
                int j = idx >> 3, kq = (idx & 7) * 4;
                int gj = j0 + j;
                float4 v = make_float4(0.f, 0.f, 0.f, 0.f);
                if (gj < N)
                    v = *(const float4*)(Bb + (long long)gj * bJ + (kt + kq));
                *(float4*)(&Bs[j][kq]) = v;
            }
        } else {
#pragma unroll
            for (int it = 0; it < 16; it++) {
                int idx = tid + it * 256;
                int j = idx & 127, k = idx >> 7;
                int gj = j0 + j;
                float v = 0.f;
                if (gj < N)
                    v = Bb[(long long)gj * bJ + (long long)(kt + k) * bK];
                Bs[j][k] = v;
            }
        }
        __syncthreads();

#pragma unroll
        for (int ks = 0; ks < 4; ks++) {
            int kb = ks * 8;
            uint32_t af[4][4];
            uint32_t bf[4][2];
#pragma unroll
            for (int mt = 0; mt < 4; mt++) {
                int r = wm * 64 + mt * 16 + gid;
                af[mt][0] = f2tf32(As[r][kb + t4]);
                af[mt][1] = f2tf32(As[r + 8][kb + t4]);
                af[mt][2] = f2tf32(As[r][kb + t4 + 4]);
                af[mt][3] = f2tf32(As[r + 8][kb + t4 + 4]);
            }
#pragma unroll
            for (int nt = 0; nt < 4; nt++) {
                int c = wn * 32 + nt * 8 + gid;
                bf[nt][0] = f2tf32(Bs[c][kb + t4]);
                bf[nt][1] = f2tf32(Bs[c][kb + t4 + 4]);
            }
#pragma unroll
            for (int mt = 0; mt < 4; mt++)
#pragma unroll
                for (int nt = 0; nt < 4; nt++) {
                    asm("mma.sync.aligned.m16n8k8.row.col.f32.tf32.tf32.f32 "
                        "{%0,%1,%2,%3}, {%4,%5,%6,%7}, {%8,%9}, {%0,%1,%2,%3};"
                        : "+f"(acc[mt][nt][0]), "+f"(acc[mt][nt][1]),
                          "+f"(acc[mt][nt][2]), "+f"(acc[mt][nt][3])
                        : "r"(af[mt][0]), "r"(af[mt][1]),
                          "r"(af[mt][2]), "r"(af[mt][3]),
                          "r"(bf[nt][0]), "r"(bf[nt][1]));
                }
        }
        __syncthreads();
    }

    // ---- epilogue ----
    float* Cb = C + (long long)bz * cB;
#pragma unroll
    for (int mt = 0; mt < 4; mt++) {
#pragma unroll
        for (int nt = 0; nt < 4; nt++) {
            int r = i0 + wm * 64 + mt * 16 + gid;
            int c = j0 + wn * 32 + nt * 8 + t4 * 2;
            if (r < M) {
                if (c < N)     Cb[(long long)r * cI + (long long)c * cJ]       = acc[mt][nt][0];
                if (c + 1 < N) Cb[(long long)r * cI + (long long)(c + 1) * cJ] = acc[mt][nt][1];
            }
            if (r + 8 < M) {
                if (c < N)     Cb[(long long)(r + 8) * cI + (long long)c * cJ]       = acc[mt][nt][2];
                if (c + 1 < N) Cb[(long long)(r + 8) * cI + (long long)(c + 1) * cJ] = acc[mt][nt][3];
            }
        }
    }
}

// ---------------- generic strided fp32 GEMM (small inner GEMMs) ------------
__global__ void gemm64(const float* __restrict__ A, const float* __restrict__ B,
                       float* __restrict__ C, int M, int N, int K,
                       long long aB, long long aI, long long aK,
                       long long bB, long long bJ, long long bK,
                       long long cB, long long cI, long long cJ)
{
    __shared__ float As[16][65];
    __shared__ float Bs[16][65];
    int bz = blockIdx.z;
    int i0 = blockIdx.y * 64;
    int j0 = blockIdx.x * 64;
    int tid = threadIdx.x;
    int tx = tid & 15, ty = tid >> 4;
    const float* Ab = A + (long long)bz * aB;
    const float* Bb = B + (long long)bz * bB;

    float acc[4][4];
#pragma unroll
    for (int r = 0; r < 4; r++)
#pragma unroll
        for (int c = 0; c < 4; c++) acc[r][c] = 0.f;

    bool aKfast = (aK == 1);
    bool bKfast = (bK == 1);

    for (int kt = 0; kt < K; kt += 16) {
#pragma unroll
        for (int t = 0; t < 4; t++) {
            int idx = tid + t * 256;
            {
                int k, i;
                if (aKfast) { k = idx & 15; i = idx >> 4; }
                else        { i = idx & 63; k = idx >> 6; }
                int gi = i0 + i, gk = kt + k;
                float v = 0.f;
                if (gi < M && gk < K)
                    v = Ab[(long long)gi * aI + (long long)gk * aK];
                As[k][i] = v;
            }
            {
                int k, j;
                if (bKfast) { k = idx & 15; j = idx >> 4; }
                else        { j = idx & 63; k = idx >> 6; }
                int gj = j0 + j, gk = kt + k;
                float v = 0.f;
                if (gj < N && gk < K)
                    v = Bb[(long long)gj * bJ + (long long)gk * bK];
                Bs[k][j] = v;
            }
        }
        __syncthreads();
#pragma unroll
        for (int kk = 0; kk < 16; kk++) {
            float a[4], b[4];
#pragma unroll
            for (int r = 0; r < 4; r++) a[r] = As[kk][ty * 4 + r];
#pragma unroll
            for (int c = 0; c < 4; c++) b[c] = Bs[kk][tx * 4 + c];
#pragma unroll
            for (int r = 0; r < 4; r++)
#pragma unroll
                for (int c = 0; c < 4; c++) acc[r][c] += a[r] * b[c];
        }
        __syncthreads();
    }

    float* Cb = C + (long long)bz * cB;
#pragma unroll
    for (int r = 0; r < 4; r++) {
        int gi = i0 + ty * 4 + r;
        if (gi >= M) continue;
#pragma unroll
        for (int c = 0; c < 4; c++) {
            int gj = j0 + tx * 4 + c;
            if (gj < N)
                Cb[(long long)gi * cI + (long long)gj * cJ] = acc[r][c];
        }
    }
}

// ---------------- depthwise causal conv1d + bias + SiLU ----------------
__global__ void conv_silu_kernel(const float* __restrict__ in, long long in_bs,
                                 const float* __restrict__ w,
                                 const float* __restrict__ bias,
                                 float* __restrict__ out,
                                 int Bn, int D, int Lx, int Kc)
{
    long long idx = (long long)blockIdx.x * blockDim.x + threadIdx.x;
    long long total = (long long)Bn * D * Lx;
    if (idx >= total) return;
    int l = (int)(idx % Lx);
    int d = (int)((idx / Lx) % D);
    int b = (int)(idx / ((long long)Lx * D));
    const float* xin = in + (long long)b * in_bs + (long long)d * Lx;
    float acc = bias[d];
    for (int k = 0; k < Kc; k++) {
        int li = l - (Kc - 1) + k;
        if (li >= 0) acc += w[d * Kc + k] * xin[li];
    }
    out[idx] = acc * (1.f / (1.f + __expf(-acc)));
}

// ---------------- selective scan ----------------
template <int NS>
__global__ void scan_kernel(const float* __restrict__ delta, long long d_bs,
                            const float* __restrict__ dt_bias,
                            const float* __restrict__ A_log,
                            const float* __restrict__ u, long long u_bs,
                            const float* __restrict__ bc, int bcRow, int bOff, int cOff,
                            const float* __restrict__ Dp,
                            const float* __restrict__ z, long long z_bs,
                            float* __restrict__ y, long long y_bs,
                            int Bn, int Dch, int Lx)
{
    const int WPC = 32 / NS;
    int lane = threadIdx.x & 31;
    int warp = (blockIdx.x * blockDim.x + threadIdx.x) >> 5;
    int n = lane % NS;
    int ch = warp * WPC + lane / NS;
    if (ch >= Bn * Dch) return;
    int b = ch / Dch, d = ch % Dch;

    float An   = -__expf(A_log[d * NS + n]);
    float Dd   = Dp[d];
    float bias = dt_bias[d];
    const float* dl  = delta + (long long)b * d_bs + (long long)d * Lx;
    const float* ul  = u     + (long long)b * u_bs + (long long)d * Lx;
    const float* zl  = z     + (long long)b * z_bs + (long long)d * Lx;
    const float* bcb = bc + (long long)b * Lx * bcRow;
    float* yl = y + (long long)b * y_bs + (long long)d * Lx;

    float s = 0.f;
    for (int l = 0; l < Lx; l++) {
        float t  = dl[l] + bias;
        float dt = (t > 20.f) ? t : log1pf(__expf(t));
        float uu = ul[l];
        const float* row = bcb + (long long)l * bcRow;
        float Bv = row[bOff + n];
        float Cv = row[cOff + n];
        s = __expf(dt * An) * s + dt * Bv * uu;
        float yp = s * Cv;
#pragma unroll
        for (int off = NS / 2; off > 0; off >>= 1)
            yp += __shfl_xor_sync(0xffffffffu, yp, off);
        if (n == 0) {
            float zz = zl[l];
            yl[l] = (yp + uu * Dd) * zz * (1.f / (1.f + __expf(-zz)));
        }
    }
}

// ---------------- launch ----------------
extern "C" void kernel_launch(void* const* d_in, const int* in_sizes, int n_in,
                              void* d_out, int out_size)
{
    const float* h         = (const float*)d_in[0];   // [2,1024,1024]
    const float* in_proj_w = (const float*)d_in[1];   // [4096,1024]
    const float* conv_w    = (const float*)d_in[2];   // [2048,4]
    const float* conv_b    = (const float*)d_in[3];   // [2048]
    const float* x_proj_w  = (const float*)d_in[4];   // [96,2048]
    const float* A_log     = (const float*)d_in[5];   // [2048,16]
    const float* Dvec      = (const float*)d_in[6];   // [2048]
    const float* dt_out_w  = (const float*)d_in[7];   // [2048,64]
    const float* dt_out_b  = (const float*)d_in[8];   // [2048]
    const float* out_w     = (const float*)d_in[9];   // [1024,2048]
    const float* m_in_w    = (const float*)d_in[10];  // [128,64]
    const float* m_conv_w  = (const float*)d_in[11];  // [64,2]
    const float* m_conv_b  = (const float*)d_in[12];  // [64]
    const float* m_x_proj_w= (const float*)d_in[13];  // [12,64]
    const float* m_dt_w    = (const float*)d_in[14];  // [64,4]
    const float* m_dt_b    = (const float*)d_in[15];  // [64]
    const float* m_A_log   = (const float*)d_in[16];  // [64,4]
    const float* m_D       = (const float*)d_in[17];  // [64]
    const float* m_out_w   = (const float*)d_in[18];  // [64,64]
    float* out = (float*)d_out;                       // [2,1024,1024]

    float *xz, *xc, *xdbl, *mxz, *mxc, *mxdbl, *mdel, *myi, *dtm, *del, *y;
    cudaGetSymbolAddress((void**)&xz,    g_xz);
    cudaGetSymbolAddress((void**)&xc,    g_xc);
    cudaGetSymbolAddress((void**)&xdbl,  g_xdbl);
    cudaGetSymbolAddress((void**)&mxz,   g_mxz);
    cudaGetSymbolAddress((void**)&mxc,   g_mxc);
    cudaGetSymbolAddress((void**)&mxdbl, g_mxdbl);
    cudaGetSymbolAddress((void**)&mdel,  g_mdel);
    cudaGetSymbolAddress((void**)&myi,   g_myi);
    cudaGetSymbolAddress((void**)&dtm,   g_dtm);
    cudaGetSymbolAddress((void**)&del,   g_del);
    cudaGetSymbolAddress((void**)&y,     g_y);

    const long long LL = L_;

    // 1) xz[b,e,l] = sum_d in_proj_w[e,d] * h[b,l,d]   (M=4096,N=1024,K=1024)
    gemm_tc<<<dim3(L_ / 128, (2 * DI_) / 128, B_), 256>>>(
        in_proj_w, h, xz, 2 * DI_, L_, DM_,
        0LL, (long long)DM_, 1LL,
        (long long)L_ * DM_, (long long)DM_, 1LL,
        (long long)2 * DI_ * L_, LL, 1LL);

    // 2) x = silu(conv(x) + b)
    {
        long long total = (long long)B_ * DI_ * L_;
        conv_silu_kernel<<<(int)((total + 255) / 256), 256>>>(
            xz, (long long)2 * DI_ * L_, conv_w, conv_b, xc, B_, DI_, L_, KC_);
    }

    // 3) x_dbl[b,l,e] = sum_d xc[b,d,l] * x_proj_w[e,d]  (M=1024,N=96,K=2048)
    gemm_tc<<<dim3(1, L_ / 128, B_), 256>>>(
        xc, x_proj_w, xdbl, L_, 96, DI_,
        (long long)DI_ * L_, 1LL, LL,
        0LL, (long long)DI_, 1LL,
        (long long)L_ * 96, 96LL, 1LL);

    // 4a) inner in_proj: mxz[b,e,l] = sum_r m_in_w[e,r] * dt_in[b,l,r]
    gemm64<<<dim3(L_ / 64, 2, B_), 256>>>(
        m_in_w, xdbl, mxz, 2 * MDI_, L_, DTR_,
        0LL, (long long)DTR_, 1LL,
        (long long)L_ * 96, 96LL, 1LL,
        (long long)2 * MDI_ * L_, LL, 1LL);

    // 4b) inner conv+silu
    {
        long long total = (long long)B_ * MDI_ * L_;
        conv_silu_kernel<<<(int)((total + 255) / 256), 256>>>(
            mxz, (long long)2 * MDI_ * L_, m_conv_w, m_conv_b, mxc, B_, MDI_, L_, MKC_);
    }

    // 4c) inner x_proj: mxdbl[b,l,e] = sum_d mxc[b,d,l] * m_x_proj_w[e,d]
    gemm64<<<dim3(1, L_ / 64, B_), 256>>>(
        mxc, m_x_proj_w, mxdbl, L_, 12, MDI_,
        (long long)MDI_ * L_, 1LL, LL,
        0LL, (long long)MDI_, 1LL,
        (long long)L_ * 12, 12LL, 1LL);

    // 4d) inner delta: mdel[b,d,l] = sum_r m_dt_w[d,r] * mxdbl[b,l,r]
    gemm64<<<dim3(L_ / 64, 1, B_), 256>>>(
        m_dt_w, mxdbl, mdel, MDI_, L_, 4,
        0LL, 4LL, 1LL,
        (long long)L_ * 12, 12LL, 1LL,
        (long long)MDI_ * L_, LL, 1LL);

    // 4e) inner scan (NS=4): 128 channels -> 2 blocks of 256
    scan_kernel<MNS_><<<2, 256>>>(
        mdel, (long long)MDI_ * L_,
        m_dt_b, m_A_log,
        mxc, (long long)MDI_ * L_,
        mxdbl, 12, 4, 8,
        m_D,
        mxz + (long long)MDI_ * L_, (long long)2 * MDI_ * L_,
        myi, (long long)MDI_ * L_,
        B_, MDI_, L_);

    // 4f) dt_m[b,l,o] = sum_d myi[b,d,l] * m_out_w[o,d]
    gemm64<<<dim3(1, L_ / 64, B_), 256>>>(
        myi, m_out_w, dtm, L_, DTR_, MDI_,
        (long long)MDI_ * L_, 1LL, LL,
        0LL, (long long)MDI_, 1LL,
        (long long)L_ * DTR_, (long long)DTR_, 1LL);

    // 5) delta[b,d,l] = sum_r dt_out_w[d,r] * dtm[b,l,r]  (M=2048,N=1024,K=64)
    gemm_tc<<<dim3(L_ / 128, DI_ / 128, B_), 256>>>(
        dt_out_w, dtm, del, DI_, L_, DTR_,
        0LL, (long long)DTR_, 1LL,
        (long long)L_ * DTR_, (long long)DTR_, 1LL,
        (long long)DI_ * L_, LL, 1LL);

    // 6) outer scan (NS=16): 4096 channels -> 256 blocks of 256
    scan_kernel<NSO_><<<256, 256>>>(
        del, (long long)DI_ * L_,
        dt_out_b, A_log,
        xc, (long long)DI_ * L_,
        xdbl, 96, 64, 80,
        Dvec,
        xz + (long long)DI_ * L_, (long long)2 * DI_ * L_,
        y, (long long)DI_ * L_,
        B_, DI_, L_);

    // 7) out[b,l,o] = sum_d y[b,d,l] * out_w[o,d]  (M=1024,N=1024,K=2048)
    gemm_tc<<<dim3(DM_ / 128, L_ / 128, B_), 256>>>(
        y, out_w, out, L_, DM_, DI_,
        (long long)DI_ * L_, 1LL, LL,
        0LL, (long long)DI_, 1LL,
        (long long)L_ * DM_, (long long)DM_, 1LL);
}

// round 4
// speedup vs baseline: 1.5465x; 1.3001x over previous
#include <cuda_runtime.h>
#include <cuda_bf16.h>
#include <cstdint>

// ---------------- problem constants ----------------
#define B_    2
#define L_    1024
#define DM_   1024
#define DI_   2048
#define NSO_  16      // outer state dim
#define KC_   4       // outer conv width
#define DTR_  64
#define MDI_  64
#define MNS_  4       // inner state dim
#define MKC_  2       // inner conv width

// ---------------- scratch (device globals; no allocation allowed) ----------
__device__ float g_xz   [(size_t)B_ * 2 * DI_ * L_];   // in_proj out [b, 2DI, L]
__device__ float g_xc   [(size_t)B_ * DI_ * L_];       // conv+silu x [b, DI, L]
__device__ float g_xdbl [(size_t)B_ * L_ * 96];        // x_proj out  [b, L, 96]
__device__ float g_mxz  [(size_t)B_ * 2 * MDI_ * L_];  // inner in_proj [b,128,L]
__device__ float g_mxc  [(size_t)B_ * MDI_ * L_];      // inner conv+silu
__device__ float g_mxdbl[(size_t)B_ * L_ * 12];        // inner x_proj [b,L,12]
__device__ float g_mdel [(size_t)B_ * MDI_ * L_];      // inner delta
__device__ float g_myi  [(size_t)B_ * MDI_ * L_];      // inner scan out
__device__ float g_dtm  [(size_t)B_ * L_ * DTR_];      // dt_m [b,L,64]
__device__ float g_del  [(size_t)B_ * DI_ * L_];       // outer delta
__device__ float g_y    [(size_t)B_ * DI_ * L_];       // outer scan out

// ================= helpers =================
__device__ __forceinline__ uint32_t smem_u32(const void* p) {
    uint32_t a;
    asm("{ .reg .u64 t; cvta.to.shared.u64 t, %1; cvt.u32.u64 %0, t; }"
        : "=r"(a) : "l"(p));
    return a;
}
__device__ __forceinline__ uint32_t f2tf32(float x) {
    uint32_t u;
    asm("cvt.rna.tf32.f32 %0, %1;" : "=r"(u) : "f"(x));
    return u;
}
__device__ __forceinline__ void cp16(uint32_t dst, const float* src, bool pred) {
    int sz = pred ? 16 : 0;
    asm volatile("cp.async.cg.shared.global [%0], [%1], 16, %2;"
                 :: "r"(dst), "l"(src), "r"(sz) : "memory");
}
__device__ __forceinline__ void cp4(uint32_t dst, const float* src, bool pred) {
    int sz = pred ? 4 : 0;
    asm volatile("cp.async.ca.shared.global [%0], [%1], 4, %2;"
                 :: "r"(dst), "l"(src), "r"(sz) : "memory");
}
__device__ __forceinline__ void cp_commit() {
    asm volatile("cp.async.commit_group;" ::: "memory");
}
template <int N>
__device__ __forceinline__ void cp_wait() {
    asm volatile("cp.async.wait_group %0;" :: "n"(N) : "memory");
}

// ---------------- pipelined tf32 tensor-core GEMM ----------------
// C[b,i,j] = sum_k A[b*aB + i*aI + k*aK] * B[b*bB + j*bJ + k*bK]
// 128x128 tile, BK=32, 3-stage cp.async pipeline, 256 threads (8 warps 2x4),
// mma.sync m16n8k8 tf32. smem rows padded to 36 floats (conflict-free frags).
// REQUIRES: M % 128 == 0, K % 32 == 0 (A side and K unguarded; B side guarded).
#define GPAD   36
#define GSTG_F (128 * GPAD)              // floats per tile
#define GSTAGE_F (2 * GSTG_F)            // A + B per stage
#define GSM_BYTES (3 * GSTAGE_F * 4)     // 110,592 B

__global__ void __launch_bounds__(256, 2) gemm_tc(
    const float* __restrict__ A, const float* __restrict__ B,
    float* __restrict__ C, int M, int N, int K,
    long long aB, long long aI, long long aK,
    long long bB, long long bJ, long long bK,
    long long cB, long long cI, long long cJ)
{
    extern __shared__ float smf[];
    uint32_t sbase = smem_u32(smf);

    int tid = threadIdx.x;
    int lane = tid & 31, warp = tid >> 5;
    int wm = warp & 1;          // 0..1  -> 64 rows each
    int wn = warp >> 1;         // 0..3  -> 32 cols each
    int gid = lane >> 2, t4 = lane & 3;

    int bz = blockIdx.z;
    int i0 = blockIdx.y * 128;
    int j0 = blockIdx.x * 128;

    const float* Ab = A + (long long)bz * aB;
    const float* Bb = B + (long long)bz * bB;

    const bool aKf = (aK == 1);
    const bool bKf = (bK == 1);
    const int nch = K >> 5;

    float acc[4][4][4] = {};

    // ---- stage issue: load chunk kt into stage s ----
    auto issue = [&](int c, int s) {
        int kt = c << 5;
        uint32_t aOff = sbase + (uint32_t)(s * GSTAGE_F) * 4;
        uint32_t bOff = aOff + (uint32_t)GSTG_F * 4;
        if (aKf) {
#pragma unroll
            for (int it = 0; it < 4; it++) {
                int idx = tid + it * 256;          // 1024 16B chunks
                int row = idx >> 3, kq = (idx & 7) * 4;
                cp16(aOff + (uint32_t)(row * GPAD + kq) * 4,
                     Ab + (long long)(i0 + row) * aI + (kt + kq), true);
            }
        } else {
#pragma unroll
            for (int it = 0; it < 16; it++) {
                int idx = tid + it * 256;          // 4096 scalars
                int row = idx & 127, k = idx >> 7;
                cp4(aOff + (uint32_t)(row * GPAD + k) * 4,
                    Ab + (long long)(i0 + row) * aI + (long long)(kt + k) * aK, true);
            }
        }
        if (bKf) {
#pragma unroll
            for (int it = 0; it < 4; it++) {
                int idx = tid + it * 256;
                int row = idx >> 3, kq = (idx & 7) * 4;
                cp16(bOff + (uint32_t)(row * GPAD + kq) * 4,
                     Bb + (long long)(j0 + row) * bJ + (kt + kq), (j0 + row) < N);
            }
        } else {
#pragma unroll
            for (int it = 0; it < 16; it++) {
                int idx = tid + it * 256;
                int row = idx & 127, k = idx >> 7;
                cp4(bOff + (uint32_t)(row * GPAD + k) * 4,
                    Bb + (long long)(j0 + row) * bJ + (long long)(kt + k) * bK,
                    (j0 + row) < N);
            }
        }
        cp_commit();
    };

    // prologue: fill stages 0 and 1
    issue(0, 0);
    if (nch > 1) issue(1, 1); else cp_commit();

    for (int c = 0; c < nch; c++) {
        cp_wait<1>();           // stage c resident
        __syncthreads();

        // prefetch stage c+2 into buffer (c+2)%3 (freed: held stage c-1)
        if (c + 2 < nch) issue(c + 2, (c + 2) % 3);
        else cp_commit();

        const float* As = smf + (c % 3) * GSTAGE_F;
        const float* Bs = As + GSTG_F;

#pragma unroll
        for (int ks = 0; ks < 4; ks++) {
            int kb = ks * 8;
            uint32_t af[4][4];
            uint32_t bf[4][2];
#pragma unroll
            for (int mt = 0; mt < 4; mt++) {
                int r = wm * 64 + mt * 16 + gid;
                af[mt][0] = f2tf32(As[r * GPAD + kb + t4]);
                af[mt][1] = f2tf32(As[(r + 8) * GPAD + kb + t4]);
                af[mt][2] = f2tf32(As[r * GPAD + kb + t4 + 4]);
                af[mt][3] = f2tf32(As[(r + 8) * GPAD + kb + t4 + 4]);
            }
#pragma unroll
            for (int nt = 0; nt < 4; nt++) {
                int cc = wn * 32 + nt * 8 + gid;
                bf[nt][0] = f2tf32(Bs[cc * GPAD + kb + t4]);
                bf[nt][1] = f2tf32(Bs[cc * GPAD + kb + t4 + 4]);
            }
#pragma unroll
            for (int mt = 0; mt < 4; mt++)
#pragma unroll
                for (int nt = 0; nt < 4; nt++) {
                    asm("mma.sync.aligned.m16n8k8.row.col.f32.tf32.tf32.f32 "
                        "{%0,%1,%2,%3}, {%4,%5,%6,%7}, {%8,%9}, {%0,%1,%2,%3};"
                        : "+f"(acc[mt][nt][0]), "+f"(acc[mt][nt][1]),
                          "+f"(acc[mt][nt][2]), "+f"(acc[mt][nt][3])
                        : "r"(af[mt][0]), "r"(af[mt][1]),
                          "r"(af[mt][2]), "r"(af[mt][3]),
                          "r"(bf[nt][0]), "r"(bf[nt][1]));
                }
        }
        __syncthreads();
    }

    // ---- epilogue ----
    float* Cb = C + (long long)bz * cB;
#pragma unroll
    for (int mt = 0; mt < 4; mt++) {
#pragma unroll
        for (int nt = 0; nt < 4; nt++) {
            int r = i0 + wm * 64 + mt * 16 + gid;
            int c = j0 + wn * 32 + nt * 8 + t4 * 2;
            if (c < N) {
                Cb[(long long)r * cI + (long long)c * cJ] = acc[mt][nt][0];
                Cb[(long long)(r + 8) * cI + (long long)c * cJ] = acc[mt][nt][2];
            }
            if (c + 1 < N) {
                Cb[(long long)r * cI + (long long)(c + 1) * cJ] = acc[mt][nt][1];
                Cb[(long long)(r + 8) * cI + (long long)(c + 1) * cJ] = acc[mt][nt][3];
            }
        }
    }
}

// ---------------- generic strided fp32 GEMM (small inner GEMMs) ------------
__global__ void gemm64(const float* __restrict__ A, const float* __restrict__ B,
                       float* __restrict__ C, int M, int N, int K,
                       long long aB, long long aI, long long aK,
                       long long bB, long long bJ, long long bK,
                       long long cB, long long cI, long long cJ)
{
    __shared__ float As[16][65];
    __shared__ float Bs[16][65];
    int bz = blockIdx.z;
    int i0 = blockIdx.y * 64;
    int j0 = blockIdx.x * 64;
    int tid = threadIdx.x;
    int tx = tid & 15, ty = tid >> 4;
    const float* Ab = A + (long long)bz * aB;
    const float* Bb = B + (long long)bz * bB;

    float acc[4][4];
#pragma unroll
    for (int r = 0; r < 4; r++)
#pragma unroll
        for (int c = 0; c < 4; c++) acc[r][c] = 0.f;

    bool aKfast = (aK == 1);
    bool bKfast = (bK == 1);

    for (int kt = 0; kt < K; kt += 16) {
#pragma unroll
        for (int t = 0; t < 4; t++) {
            int idx = tid + t * 256;
            {
                int k, i;
                if (aKfast) { k = idx & 15; i = idx >> 4; }
                else        { i = idx & 63; k = idx >> 6; }
                int gi = i0 + i, gk = kt + k;
                float v = 0.f;
                if (gi < M && gk < K)
                    v = Ab[(long long)gi * aI + (long long)gk * aK];
                As[k][i] = v;
            }
            {
                int k, j;
                if (bKfast) { k = idx & 15; j = idx >> 4; }
                else        { j = idx & 63; k = idx >> 6; }
                int gj = j0 + j, gk = kt + k;
                float v = 0.f;
                if (gj < N && gk < K)
                    v = Bb[(long long)gj * bJ + (long long)gk * bK];
                Bs[k][j] = v;
            }
        }
        __syncthreads();
#pragma unroll
        for (int kk = 0; kk < 16; kk++) {
            float a[4], b[4];
#pragma unroll
            for (int r = 0; r < 4; r++) a[r] = As[kk][ty * 4 + r];
#pragma unroll
            for (int c = 0; c < 4; c++) b[c] = Bs[kk][tx * 4 + c];
#pragma unroll
            for (int r = 0; r < 4; r++)
#pragma unroll
                for (int c = 0; c < 4; c++) acc[r][c] += a[r] * b[c];
        }
        __syncthreads();
    }

    float* Cb = C + (long long)bz * cB;
#pragma unroll
    for (int r = 0; r < 4; r++) {
        int gi = i0 + ty * 4 + r;
        if (gi >= M) continue;
#pragma unroll
        for (int c = 0; c < 4; c++) {
            int gj = j0 + tx * 4 + c;
            if (gj < N)
                Cb[(long long)gi * cI + (long long)gj * cJ] = acc[r][c];
        }
    }
}

// ---------------- depthwise causal conv1d + bias + SiLU ----------------
__global__ void conv_silu_kernel(const float* __restrict__ in, long long in_bs,
                                 const float* __restrict__ w,
                                 const float* __restrict__ bias,
                                 float* __restrict__ out,
                                 int Bn, int D, int Lx, int Kc)
{
    long long idx = (long long)blockIdx.x * blockDim.x + threadIdx.x;
    long long total = (long long)Bn * D * Lx;
    if (idx >= total) return;
    int l = (int)(idx % Lx);
    int d = (int)((idx / Lx) % D);
    int b = (int)(idx / ((long long)Lx * D));
    const float* xin = in + (long long)b * in_bs + (long long)d * Lx;
    float acc = bias[d];
    for (int k = 0; k < Kc; k++) {
        int li = l - (Kc - 1) + k;
        if (li >= 0) acc += w[d * Kc + k] * xin[li];
    }
    out[idx] = acc * (1.f / (1.f + __expf(-acc)));
}

// ---------------- selective scan ----------------
template <int NS>
__global__ void scan_kernel(const float* __restrict__ delta, long long d_bs,
                            const float* __restrict__ dt_bias,
                            const float* __restrict__ A_log,
                            const float* __restrict__ u, long long u_bs,
                            const float* __restrict__ bc, int bcRow, int bOff, int cOff,
                            const float* __restrict__ Dp,
                            const float* __restrict__ z, long long z_bs,
                            float* __restrict__ y, long long y_bs,
                            int Bn, int Dch, int Lx)
{
    const int WPC = 32 / NS;
    int lane = threadIdx.x & 31;
    int warp = (blockIdx.x * blockDim.x + threadIdx.x) >> 5;
    int n = lane % NS;
    int ch = warp * WPC + lane / NS;
    if (ch >= Bn * Dch) return;
    int b = ch / Dch, d = ch % Dch;

    float An   = -__expf(A_log[d * NS + n]);
    float Dd   = Dp[d];
    float bias = dt_bias[d];
    const float* dl  = delta + (long long)b * d_bs + (long long)d * Lx;
    const float* ul  = u     + (long long)b * u_bs + (long long)d * Lx;
    const float* zl  = z     + (long long)b * z_bs + (long long)d * Lx;
    const float* bcb = bc + (long long)b * Lx * bcRow;
    float* yl = y + (long long)b * y_bs + (long long)d * Lx;

    float s = 0.f;
    for (int l = 0; l < Lx; l++) {
        float t  = dl[l] + bias;
        float dt = (t > 20.f) ? t : log1pf(__expf(t));
        float uu = ul[l];
        const float* row = bcb + (long long)l * bcRow;
        float Bv = row[bOff + n];
        float Cv = row[cOff + n];
        s = __expf(dt * An) * s + dt * Bv * uu;
        float yp = s * Cv;
#pragma unroll
        for (int off = NS / 2; off > 0; off >>= 1)
            yp += __shfl_xor_sync(0xffffffffu, yp, off);
        if (n == 0) {
            float zz = zl[l];
            yl[l] = (yp + uu * Dd) * zz * (1.f / (1.f + __expf(-zz)));
        }
    }
}

// ---------------- launch ----------------
extern "C" void kernel_launch(void* const* d_in, const int* in_sizes, int n_in,
                              void* d_out, int out_size)
{
    const float* h         = (const float*)d_in[0];   // [2,1024,1024]
    const float* in_proj_w = (const float*)d_in[1];   // [4096,1024]
    const float* conv_w    = (const float*)d_in[2];   // [2048,4]
    const float* conv_b    = (const float*)d_in[3];   // [2048]
    const float* x_proj_w  = (const float*)d_in[4];   // [96,2048]
    const float* A_log     = (const float*)d_in[5];   // [2048,16]
    const float* Dvec      = (const float*)d_in[6];   // [2048]
    const float* dt_out_w  = (const float*)d_in[7];   // [2048,64]
    const float* dt_out_b  = (const float*)d_in[8];   // [2048]
    const float* out_w     = (const float*)d_in[9];   // [1024,2048]
    const float* m_in_w    = (const float*)d_in[10];  // [128,64]
    const float* m_conv_w  = (const float*)d_in[11];  // [64,2]
    const float* m_conv_b  = (const float*)d_in[12];  // [64]
    const float* m_x_proj_w= (const float*)d_in[13];  // [12,64]
    const float* m_dt_w    = (const float*)d_in[14];  // [64,4]
    const float* m_dt_b    = (const float*)d_in[15];  // [64]
    const float* m_A_log   = (const float*)d_in[16];  // [64,4]
    const float* m_D       = (const float*)d_in[17];  // [64]
    const float* m_out_w   = (const float*)d_in[18];  // [64,64]
    float* out = (float*)d_out;                       // [2,1024,1024]

    float *xz, *xc, *xdbl, *mxz, *mxc, *mxdbl, *mdel, *myi, *dtm, *del, *y;
    cudaGetSymbolAddress((void**)&xz,    g_xz);
    cudaGetSymbolAddress((void**)&xc,    g_xc);
    cudaGetSymbolAddress((void**)&xdbl,  g_xdbl);
    cudaGetSymbolAddress((void**)&mxz,   g_mxz);
    cudaGetSymbolAddress((void**)&mxc,   g_mxc);
    cudaGetSymbolAddress((void**)&mxdbl, g_mxdbl);
    cudaGetSymbolAddress((void**)&mdel,  g_mdel);
    cudaGetSymbolAddress((void**)&myi,   g_myi);
    cudaGetSymbolAddress((void**)&dtm,   g_dtm);
    cudaGetSymbolAddress((void**)&del,   g_del);
    cudaGetSymbolAddress((void**)&y,     g_y);

    cudaFuncSetAttribute(gemm_tc,
                         cudaFuncAttributeMaxDynamicSharedMemorySize, GSM_BYTES);

    const long long LL = L_;

    // 1) xz[b,e,l] = sum_d in_proj_w[e,d] * h[b,l,d]   (M=4096,N=1024,K=1024)
    gemm_tc<<<dim3(L_ / 128, (2 * DI_) / 128, B_), 256, GSM_BYTES>>>(
        in_proj_w, h, xz, 2 * DI_, L_, DM_,
        0LL, (long long)DM_, 1LL,
        (long long)L_ * DM_, (long long)DM_, 1LL,
        (long long)2 * DI_ * L_, LL, 1LL);

    // 2) x = silu(conv(x) + b)
    {
        long long total = (long long)B_ * DI_ * L_;
        conv_silu_kernel<<<(int)((total + 255) / 256), 256>>>(
            xz, (long long)2 * DI_ * L_, conv_w, conv_b, xc, B_, DI_, L_, KC_);
    }

    // 3) x_dbl[b,l,e] = sum_d xc[b,d,l] * x_proj_w[e,d]  (M=1024,N=96,K=2048)
    gemm_tc<<<dim3(1, L_ / 128, B_), 256, GSM_BYTES>>>(
        xc, x_proj_w, xdbl, L_, 96, DI_,
        (long long)DI_ * L_, 1LL, LL,
        0LL, (long long)DI_, 1LL,
        (long long)L_ * 96, 96LL, 1LL);

    // 4a) inner in_proj: mxz[b,e,l] = sum_r m_in_w[e,r] * dt_in[b,l,r]
    gemm64<<<dim3(L_ / 64, 2, B_), 256>>>(
        m_in_w, xdbl, mxz, 2 * MDI_, L_, DTR_,
        0LL, (long long)DTR_, 1LL,
        (long long)L_ * 96, 96LL, 1LL,
        (long long)2 * MDI_ * L_, LL, 1LL);

    // 4b) inner conv+silu
    {
        long long total = (long long)B_ * MDI_ * L_;
        conv_silu_kernel<<<(int)((total + 255) / 256), 256>>>(
            mxz, (long long)2 * MDI_ * L_, m_conv_w, m_conv_b, mxc, B_, MDI_, L_, MKC_);
    }

    // 4c) inner x_proj: mxdbl[b,l,e] = sum_d mxc[b,d,l] * m_x_proj_w[e,d]
    gemm64<<<dim3(1, L_ / 64, B_), 256>>>(
        mxc, m_x_proj_w, mxdbl, L_, 12, MDI_,
        (long long)MDI_ * L_, 1LL, LL,
        0LL, (long long)MDI_, 1LL,
        (long long)L_ * 12, 12LL, 1LL);

    // 4d) inner delta: mdel[b,d,l] = sum_r m_dt_w[d,r] * mxdbl[b,l,r]
    gemm64<<<dim3(L_ / 64, 1, B_), 256>>>(
        m_dt_w, mxdbl, mdel, MDI_, L_, 4,
        0LL, 4LL, 1LL,
        (long long)L_ * 12, 12LL, 1LL,
        (long long)MDI_ * L_, LL, 1LL);

    // 4e) inner scan (NS=4): 128 channels -> 2 blocks of 256
    scan_kernel<MNS_><<<2, 256>>>(
        mdel, (long long)MDI_ * L_,
        m_dt_b, m_A_log,
        mxc, (long long)MDI_ * L_,
        mxdbl, 12, 4, 8,
        m_D,
        mxz + (long long)MDI_ * L_, (long long)2 * MDI_ * L_,
        myi, (long long)MDI_ * L_,
        B_, MDI_, L_);

    // 4f) dt_m[b,l,o] = sum_d myi[b,d,l] * m_out_w[o,d]
    gemm64<<<dim3(1, L_ / 64, B_), 256>>>(
        myi, m_out_w, dtm, L_, DTR_, MDI_,
        (long long)MDI_ * L_, 1LL, LL,
        0LL, (long long)MDI_, 1LL,
        (long long)L_ * DTR_, (long long)DTR_, 1LL);

    // 5) delta[b,d,l] = sum_r dt_out_w[d,r] * dtm[b,l,r]  (M=2048,N=1024,K=64)
    gemm_tc<<<dim3(L_ / 128, DI_ / 128, B_), 256, GSM_BYTES>>>(
        dt_out_w, dtm, del, DI_, L_, DTR_,
        0LL, (long long)DTR_, 1LL,
        (long long)L_ * DTR_, (long long)DTR_, 1LL,
        (long long)DI_ * L_, LL, 1LL);

    // 6) outer scan (NS=16): 4096 channels -> 256 blocks of 256
    scan_kernel<NSO_><<<256, 256>>>(
        del, (long long)DI_ * L_,
        dt_out_b, A_log,
        xc, (long long)DI_ * L_,
        xdbl, 96, 64, 80,
        Dvec,
        xz + (long long)DI_ * L_, (long long)2 * DI_ * L_,
        y, (long long)DI_ * L_,
        B_, DI_, L_);

    // 7) out[b,l,o] = sum_d y[b,d,l] * out_w[o,d]  (M=1024,N=1024,K=2048)
    gemm_tc<<<dim3(DM_ / 128, L_ / 128, B_), 256, GSM_BYTES>>>(
        y, out_w, out, L_, DM_, DI_,
        (long long)DI_ * L_, 1LL, LL,
        0LL, (long long)DI_, 1LL,
        (long long)L_ * DM_, (long long)DM_, 1LL);
}